// round 10
// baseline (speedup 1.0000x reference)
#include <cuda_runtime.h>

// Round 10: R9 champion (decoupled L1/L2 groups, named barriers, 4-deep
// handoff ring) with a shortened tail:
//  - gates are PRE-ACTIVATED before the xor2 gate exchange (branchless
//    unified sigma/tanh ladder selected by per-thread constants), so the
//    MUFU ladders overlap the shfl latency instead of following it;
//  - biases are seeded into the kh=0 accumulators via the f32x2 lane trick
//    (pk2(bias,0)), deleting the 4 post-exchange FADDs per thread per step.

#define T_STEPS 1000

__device__ __forceinline__ float sigf(float x) {
    float e = exp2f(-1.4426950408889634f * x);
    return __fdividef(1.0f, 1.0f + e);
}
__device__ __forceinline__ float tanh_fast(float x) {
    x = fminf(16.0f, fmaxf(-16.0f, x));
    float e = exp2f(-2.8853900817779268f * x);   // exp(-2x)
    return __fdividef(1.0f - e, 1.0f + e);
}
__device__ __forceinline__ double pk2(float lo, float hi) {
    double r; asm("mov.b64 %0, {%1,%2};" : "=d"(r) : "f"(lo), "f"(hi)); return r;
}
__device__ __forceinline__ void upk2(double v, float &lo, float &hi) {
    asm("mov.b64 {%0,%1}, %2;" : "=f"(lo), "=f"(hi) : "d"(v));
}
__device__ __forceinline__ void fma2(double &acc, double a, double b) {
    asm("fma.rn.f32x2 %0, %1, %2, %0;" : "+d"(acc) : "d"(a), "d"(b));
}
__device__ __forceinline__ float fold(double v) {
    float lo, hi; upk2(v, lo, hi); return lo + hi;
}
__device__ __forceinline__ int ld_acq(const int* p) {
    int v;
    unsigned a = (unsigned)__cvta_generic_to_shared(p);
    asm volatile("ld.acquire.cta.shared.b32 %0, [%1];" : "=r"(v) : "r"(a) : "memory");
    return v;
}
__device__ __forceinline__ void st_rel(int* p, int v) {
    unsigned a = (unsigned)__cvta_generic_to_shared(p);
    asm volatile("st.release.cta.shared.b32 [%0], %1;" :: "r"(a), "r"(v) : "memory");
}
#define WAIT_GE(fp, tgt) while (ld_acq(fp) < (tgt)) { }

__global__ void __launch_bounds__(384, 1)
audio_lstm_kernel(const float* __restrict__ x,
                  const float* __restrict__ w_ih1, const float* __restrict__ w_hh1,
                  const float* __restrict__ b_ih1, const float* __restrict__ b_hh1,
                  const float* __restrict__ w_ih2, const float* __restrict__ w_hh2,
                  const float* __restrict__ b_ih2, const float* __restrict__ b_hh2,
                  const float* __restrict__ w_fc1, const float* __restrict__ b_fc1,
                  const float* __restrict__ w_fc2, const float* __restrict__ b_fc2,
                  float* __restrict__ out)
{
    // h1 pair rows (L1-internal), double buffered
    __shared__ __align__(16) float v1h[2][32][8];
    // x pair rows 0..12 + pad row 13 (L1-internal), double buffered
    __shared__ __align__(16) float xbuf[2][14][8];
    // handoff ring: pairs 0..31 = h1 (written by L1), 32..47 = h2 (L2-internal)
    __shared__ __align__(16) float v2s[4][48][8];
    __shared__ float sf[4][16];
    __shared__ int flag1, flag2;

    const int tid = threadIdx.x;
    const int bbase = blockIdx.x * 4;
    const bool isL1 = tid < 256;

    // Role-shared registers
    double whA[16], whB[16];     // L1: h-part weights / L2: first 16 pairs
    double wxA[8], wxB[8];       // L1: x-part weights / L2: last 8 pairs
    double seedA, seedB;         // kh==0: pk2(bias,0) ; kh==1: 0
    float kA, nA;                // unified gate-A activation constants
    float c = 0.0f;
    int u, sel, kh;

    if (isL1) {
        u = tid >> 2; sel = (tid >> 1) & 1; kh = tid & 1;
        const int gA = sel ? (128 + u) : u;          // g : i
        const int gB = sel ? (192 + u) : (64 + u);   // o : f
#pragma unroll
        for (int j = 0; j < 7; j++) {                // x pairs: p = 2j+kh < 13
            int p = 2 * j + kh;
            float a0 = 0.f, a1 = 0.f, q0 = 0.f, q1 = 0.f;
            if (p < 13) {
                int k0 = 2 * p, k1 = 2 * p + 1;
                a0 = w_ih1[gA * 26 + k0]; a1 = w_ih1[gA * 26 + k1];
                q0 = w_ih1[gB * 26 + k0]; q1 = w_ih1[gB * 26 + k1];
            }
            wxA[j] = pk2(a0, a1); wxB[j] = pk2(q0, q1);
        }
        wxA[7] = 0.0; wxB[7] = 0.0;
#pragma unroll
        for (int j = 0; j < 16; j++) {               // h pairs: p = 2j+kh < 32
            int p = 2 * j + kh;
            int k0 = 2 * p, k1 = 2 * p + 1;          // h index 0..63
            whA[j] = pk2(w_hh1[gA * 64 + k0], w_hh1[gA * 64 + k1]);
            whB[j] = pk2(w_hh1[gB * 64 + k0], w_hh1[gB * 64 + k1]);
        }
        float biasA = b_ih1[gA] + b_hh1[gA];
        float biasB = b_ih1[gB] + b_hh1[gB];
        seedA = kh ? 0.0 : pk2(biasA, 0.0f);
        seedB = kh ? 0.0 : pk2(biasB, 0.0f);
    } else {
        const int t2 = tid - 256;
        u = t2 >> 2; sel = (t2 >> 1) & 1; kh = t2 & 1;
        const int gA = sel ? (64 + u) : u;
        const int gB = sel ? (96 + u) : (32 + u);
#pragma unroll
        for (int kk = 0; kk < 24; kk++) {
            int p = kh * 24 + kk;
            int k0 = 2 * p, k1 = 2 * p + 1;
            float a0 = (k0 < 64) ? w_ih2[gA * 64 + k0] : w_hh2[gA * 32 + k0 - 64];
            float a1 = (k1 < 64) ? w_ih2[gA * 64 + k1] : w_hh2[gA * 32 + k1 - 64];
            float q0 = (k0 < 64) ? w_ih2[gB * 64 + k0] : w_hh2[gB * 32 + k0 - 64];
            float q1 = (k1 < 64) ? w_ih2[gB * 64 + k1] : w_hh2[gB * 32 + k1 - 64];
            if (kk < 16) { whA[kk] = pk2(a0, a1); whB[kk] = pk2(q0, q1); }
            else         { wxA[kk - 16] = pk2(a0, a1); wxB[kk - 16] = pk2(q0, q1); }
        }
        float biasA = b_ih2[gA] + b_hh2[gA];
        float biasB = b_ih2[gB] + b_hh2[gB];
        seedA = kh ? 0.0 : pk2(biasA, 0.0f);
        seedB = kh ? 0.0 : pk2(biasB, 0.0f);
    }
    // unified gate-A activation: sel=0 -> sigmoid, sel=1 -> tanh
    kA = sel ? -2.8853900817779268f : -1.4426950408889634f;
    nA = sel ? -1.0f : 0.0f;

    const int hrow = u >> 1;
    const int hlane = u & 1;
    const int myb = 2 * kh + sel;

    // Zero buffers + init flags
    for (int idx = tid; idx < 2 * 32 * 8; idx += 384) ((float*)v1h)[idx] = 0.0f;
    for (int idx = tid; idx < 2 * 14 * 8; idx += 384) ((float*)xbuf)[idx] = 0.0f;
    for (int idx = tid; idx < 4 * 48 * 8; idx += 384) ((float*)v2s)[idx] = 0.0f;
    if (tid == 0) { flag1 = -1; flag2 = 0; }

    // x layout: x[b][i][t]  (loaders are L1 threads)
    const int xi = tid % 26;
    const int xb = tid / 26;
    const bool isldr = tid < 104;
    const int xrow = xi >> 1, xcol = xb * 2 + (xi & 1);
    const float* xptr = x + (size_t)(bbase + xb) * 26 * T_STEPS + (size_t)xi * T_STEPS;
    __syncthreads();
    if (isldr) {
        xbuf[0][xrow][xcol] = xptr[0];
        xbuf[1][xrow][xcol] = xptr[1];
    }
    __syncthreads();

    // carried x-part accumulators (bias-seeded)
    double xA0 = seedA, xA1 = seedA, xA2 = seedA, xA3 = seedA;
    double xB0 = seedB, xB1 = seedB, xB2 = seedB, xB3 = seedB;
    if (isL1) {   // precompute x-part for step 0 from xbuf[0]
#pragma unroll
        for (int j = 0; j < 7; j++) {
            const float* r = &xbuf[0][2 * j + kh][0];
            double2 vlo = *(const double2*)r;
            double2 vhi = *(const double2*)(r + 4);
            fma2(xA0, wxA[j], vlo.x); fma2(xA1, wxA[j], vlo.y);
            fma2(xA2, wxA[j], vhi.x); fma2(xA3, wxA[j], vhi.y);
            fma2(xB0, wxB[j], vlo.x); fma2(xB1, wxB[j], vlo.y);
            fma2(xB2, wxB[j], vhi.x); fma2(xB3, wxB[j], vhi.y);
        }
    }

    // shared tail: from folded partials (bias already inside via seed) to h.
    // mA0/mA1 = gate A pre-acts for batches 2kh+0 / 2kh+1, similarly B.
#define TAIL(pA0, pA1, pA2, pA3, pB0, pB1, pB2, pB3, H)                            \
    {                                                                              \
        float sA0 = kh ? pA0 : pA2, sA1 = kh ? pA1 : pA3;                          \
        float sB0 = kh ? pB0 : pB2, sB1 = kh ? pB1 : pB3;                          \
        sA0 = __shfl_xor_sync(0xffffffffu, sA0, 1);                                \
        sA1 = __shfl_xor_sync(0xffffffffu, sA1, 1);                                \
        sB0 = __shfl_xor_sync(0xffffffffu, sB0, 1);                                \
        sB1 = __shfl_xor_sync(0xffffffffu, sB1, 1);                                \
        float mA0 = (kh ? pA2 : pA0) + sA0;                                        \
        float mA1 = (kh ? pA3 : pA1) + sA1;                                        \
        float mB0 = (kh ? pB2 : pB0) + sB0;                                        \
        float mB1 = (kh ? pB3 : pB1) + sB1;                                        \
        /* pre-activate gate A (unified sigma/tanh) and gate B (sigma) */          \
        float cA0 = fminf(16.0f, fmaxf(-16.0f, mA0));                              \
        float cA1 = fminf(16.0f, fmaxf(-16.0f, mA1));                              \
        float eA0 = exp2f(kA * cA0), eA1 = exp2f(kA * cA1);                        \
        float actA0 = __fdividef(fmaf(nA, eA0, 1.0f), 1.0f + eA0);                 \
        float actA1 = __fdividef(fmaf(nA, eA1, 1.0f), 1.0f + eA1);                 \
        float actB0 = sigf(mB0), actB1 = sigf(mB1);                                \
        /* exchange activated gates with the other gate-pair thread */             \
        float rA = __shfl_xor_sync(0xffffffffu, sel ? actA0 : actA1, 2);           \
        float rB = __shfl_xor_sync(0xffffffffu, sel ? actB0 : actB1, 2);           \
        float ownA = sel ? actA1 : actA0, ownB = sel ? actB1 : actB0;              \
        float gi = sel ? rA : ownA;                                                \
        float gf = sel ? rB : ownB;                                                \
        float gg = sel ? ownA : rA;                                                \
        float go = sel ? ownB : rB;                                                \
        c = fmaf(gf, c, gi * gg);                                                  \
        H = go * tanh_fast(c);                                                     \
    }

    // L1 body at iter n
#define L1BODY(n, cur, nxt, vb)                                                    \
    {                                                                              \
        float xr = 0.0f;                                                           \
        const bool ldr = isldr && ((n) + 2 < T_STEPS);                             \
        if (ldr) xr = xptr[(n) + 2];                                               \
        double aA0 = xA0, aA1 = xA1, aA2 = xA2, aA3 = xA3;                         \
        double aB0 = xB0, aB1 = xB1, aB2 = xB2, aB3 = xB3;                         \
        _Pragma("unroll")                                                          \
        for (int j = 0; j < 16; j++) {                                             \
            const float* r = &v1h[cur][2 * j + kh][0];                             \
            double2 vlo = *(const double2*)r;                                      \
            double2 vhi = *(const double2*)(r + 4);                                \
            fma2(aA0, whA[j], vlo.x); fma2(aA1, whA[j], vlo.y);                    \
            fma2(aA2, whA[j], vhi.x); fma2(aA3, whA[j], vhi.y);                    \
            fma2(aB0, whB[j], vlo.x); fma2(aB1, whB[j], vlo.y);                    \
            fma2(aB2, whB[j], vhi.x); fma2(aB3, whB[j], vhi.y);                    \
        }                                                                          \
        float pA0 = fold(aA0), pA1 = fold(aA1), pA2 = fold(aA2), pA3 = fold(aA3);  \
        float pB0 = fold(aB0), pB1 = fold(aB1), pB2 = fold(aB2), pB3 = fold(aB3);  \
        float h;                                                                   \
        TAIL(pA0, pA1, pA2, pA3, pB0, pB1, pB2, pB3, h)                            \
        WAIT_GE(&flag2, (n) - 3);   /* ring slot vb free? (3-step slack) */        \
        v1h[nxt][hrow][myb * 2 + hlane] = h;                                       \
        v2s[vb][hrow][myb * 2 + hlane] = h;                                        \
        if (ldr) xbuf[cur][xrow][xcol] = xr;                                       \
        if ((n) + 1 < T_STEPS) {                                                   \
            xA0 = seedA; xA1 = seedA; xA2 = seedA; xA3 = seedA;                    \
            xB0 = seedB; xB1 = seedB; xB2 = seedB; xB3 = seedB;                    \
            _Pragma("unroll")                                                      \
            for (int j = 0; j < 7; j++) {                                          \
                const float* r = &xbuf[nxt][2 * j + kh][0];                        \
                double2 vlo = *(const double2*)r;                                  \
                double2 vhi = *(const double2*)(r + 4);                            \
                fma2(xA0, wxA[j], vlo.x); fma2(xA1, wxA[j], vlo.y);                \
                fma2(xA2, wxA[j], vhi.x); fma2(xA3, wxA[j], vhi.y);                \
                fma2(xB0, wxB[j], vlo.x); fma2(xB1, wxB[j], vlo.y);                \
                fma2(xB2, wxB[j], vhi.x); fma2(xB3, wxB[j], vhi.y);                \
            }                                                                      \
        }                                                                          \
        asm volatile("bar.sync 1, 256;" ::: "memory");                             \
        if (tid == 0) st_rel(&flag1, (n));                                         \
    }

    // L2 body at iter n (computes LSTM-2 step n-1)
#define L2BODY(n, rd, wr)                                                          \
    {                                                                              \
        WAIT_GE(&flag1, (n) - 1);   /* h1 of step n-1 published? */                \
        double aA0 = seedA, aA1 = seedA, aA2 = seedA, aA3 = seedA;                 \
        double aB0 = seedB, aB1 = seedB, aB2 = seedB, aB3 = seedB;                 \
        const float* base = &v2s[rd][kh * 24][0];                                  \
        _Pragma("unroll")                                                          \
        for (int kk = 0; kk < 24; kk++) {                                          \
            const float* r = base + 8 * kk;                                        \
            double2 vlo = *(const double2*)r;                                      \
            double2 vhi = *(const double2*)(r + 4);                                \
            double wa = (kk < 16) ? whA[kk] : wxA[kk - 16];                        \
            double wb = (kk < 16) ? whB[kk] : wxB[kk - 16];                        \
            fma2(aA0, wa, vlo.x); fma2(aA1, wa, vlo.y);                            \
            fma2(aA2, wa, vhi.x); fma2(aA3, wa, vhi.y);                            \
            fma2(aB0, wb, vlo.x); fma2(aB1, wb, vlo.y);                            \
            fma2(aB2, wb, vhi.x); fma2(aB3, wb, vhi.y);                            \
        }                                                                          \
        float pA0 = fold(aA0), pA1 = fold(aA1), pA2 = fold(aA2), pA3 = fold(aA3);  \
        float pB0 = fold(aB0), pB1 = fold(aB1), pB2 = fold(aB2), pB3 = fold(aB3);  \
        float h;                                                                   \
        TAIL(pA0, pA1, pA2, pA3, pB0, pB1, pB2, pB3, h)                            \
        v2s[wr][32 + hrow][myb * 2 + hlane] = h;                                   \
        asm volatile("bar.sync 2, 128;" ::: "memory");                             \
        if (tid == 256) st_rel(&flag2, (n));                                       \
    }

    if (isL1) {
        for (int n = 0; n < T_STEPS; n += 4) {
            L1BODY(n,     0, 1, 0);
            L1BODY(n + 1, 1, 0, 1);
            L1BODY(n + 2, 0, 1, 2);
            L1BODY(n + 3, 1, 0, 3);
        }
    } else {
        for (int n = 1; n <= T_STEPS; n += 4) {
            L2BODY(n,     0, 1);
            L2BODY(n + 1, 1, 2);
            L2BODY(n + 2, 2, 3);
            L2BODY(n + 3, 3, 0);
        }
    }
#undef L1BODY
#undef L2BODY
#undef TAIL
    __syncthreads();

    // ================= MLP head =================
    // final h2 (step 999, L2 iter 1000) is in v2s[0] pairs 32..47
    if (tid < 64) {
        const int b = tid >> 4, j = tid & 15;
        float s = b_fc1[j];
#pragma unroll
        for (int k2 = 0; k2 < 32; k2++)
            s = fmaf(v2s[0][32 + (k2 >> 1)][b * 2 + (k2 & 1)], w_fc1[j * 32 + k2], s);
        sf[b][j] = fmaxf(s, 0.0f);
    }
    __syncthreads();
    if (tid < 40) {
        const int b = tid / 10, o = tid % 10;
        float s = b_fc2[o];
#pragma unroll
        for (int j = 0; j < 16; j++) s = fmaf(sf[b][j], w_fc2[o * 16 + j], s);
        out[(bbase + b) * 10 + o] = s;
    }
}

extern "C" void kernel_launch(void* const* d_in, const int* in_sizes, int n_in,
                              void* d_out, int out_size)
{
    const float* x     = (const float*)d_in[0];
    const float* w_ih1 = (const float*)d_in[1];
    const float* w_hh1 = (const float*)d_in[2];
    const float* b_ih1 = (const float*)d_in[3];
    const float* b_hh1 = (const float*)d_in[4];
    const float* w_ih2 = (const float*)d_in[5];
    const float* w_hh2 = (const float*)d_in[6];
    const float* b_ih2 = (const float*)d_in[7];
    const float* b_hh2 = (const float*)d_in[8];
    const float* w_fc1 = (const float*)d_in[9];
    const float* b_fc1 = (const float*)d_in[10];
    const float* w_fc2 = (const float*)d_in[11];
    const float* b_fc2 = (const float*)d_in[12];
    float* out = (float*)d_out;

    audio_lstm_kernel<<<128, 384>>>(x, w_ih1, w_hh1, b_ih1, b_hh1,
                                    w_ih2, w_hh2, b_ih2, b_hh2,
                                    w_fc1, b_fc1, w_fc2, b_fc2, out);
}